// round 5
// baseline (speedup 1.0000x reference)
#include <cuda_runtime.h>

#define FULL_MASK 0xFFFFFFFFu

__device__ __forceinline__ unsigned long long mk_policy_last() {
    unsigned long long pol;
    asm volatile("createpolicy.fractional.L2::evict_last.b64 %0, 1.0;" : "=l"(pol));
    return pol;
}
__device__ __forceinline__ unsigned long long mk_policy_first() {
    unsigned long long pol;
    asm volatile("createpolicy.fractional.L2::evict_first.b64 %0, 1.0;" : "=l"(pol));
    return pol;
}

__device__ __forceinline__ float2 ldg_feat2(const float2* p, unsigned long long pol) {
    float2 v;
    asm volatile("ld.global.nc.L2::cache_hint.v2.f32 {%0,%1}, [%2], %3;"
                 : "=f"(v.x), "=f"(v.y) : "l"(p), "l"(pol));
    return v;
}
__device__ __forceinline__ float ldg_stream_f(const float* p, unsigned long long pol) {
    float v;
    asm volatile("ld.global.nc.L2::cache_hint.f32 %0, [%1], %2;"
                 : "=f"(v) : "l"(p), "l"(pol));
    return v;
}
__device__ __forceinline__ int ldg_stream_i(const int* p, unsigned long long pol) {
    int v;
    asm volatile("ld.global.nc.L2::cache_hint.s32 %0, [%1], %2;"
                 : "=r"(v) : "l"(p), "l"(pol));
    return v;
}
__device__ __forceinline__ void stg_stream_f(float* p, float v, unsigned long long pol) {
    asm volatile("st.global.L2::cache_hint.f32 [%0], %1, %2;"
                 :: "l"(p), "f"(v), "l"(pol) : "memory");
}

// Problem constants
// B=8, H=256, W=256, K=8, C=64, N=B*H*W=524288
// R_NDC = 1.5/256*2 = 3/256; R_NDC^2 = 9/65536 (exact in binary)
__global__ __launch_bounds__(256, 4) void rast_blend_kernel(
    const float* __restrict__ dist,
    const float* __restrict__ zbuf,
    const int*   __restrict__ pidx,
    const float* __restrict__ feat,
    float*       __restrict__ out)
{
    constexpr int C = 64;
    constexpr int K = 8;
    constexpr float INV_R2 = 65536.0f / 9.0f;

    __shared__ float s[C * 33];   // [channel][pixel-in-tile], pad 33 for readout

    const int tid = threadIdx.x;
    const int wp  = tid >> 5;     // warp id 0..7
    const int l   = tid & 31;     // lane

    const int tileBase = blockIdx.x * 32;     // first pixel (linear over B*H*W)
    const int warpPix  = tileBase + wp * 4;   // this warp: 4 consecutive pixels

    const unsigned long long polL = mk_policy_last();   // gather table: keep in L2
    const unsigned long long polF = mk_policy_first();  // streams: evict first

    // ---- header: 4 pixels x K=8 = 32 contiguous entries, one coalesced load each ----
    const long hdr = (long)warpPix * K + l;
    float d  = ldg_stream_f(dist + hdr, polF);
    float z  = ldg_stream_f(zbuf + hdr, polF);
    int   id = ldg_stream_i(pidx + hdr, polF);

    float a = 1.0f - sqrtf(fminf(fmaxf(d * INV_R2, 0.001f), 1.0f));
    bool valid = (z >= 0.0f) && (id >= 0);
    a  = valid ? a : 0.0f;
    id = (id < 0) ? 0 : id;       // safe gather index (weight already zeroed)

    const float2* __restrict__ f2 = reinterpret_cast<const float2*>(feat);

    #pragma unroll
    for (int p = 0; p < 4; ++p) {
        // batch: issue all 8 row gathers before consuming any (MLP = 8)
        float2 f[K];
        float  w[K];
        float  T = 1.0f;
        #pragma unroll
        for (int k = 0; k < K; ++k) {
            float ak = __shfl_sync(FULL_MASK, a,  p * 8 + k);
            int   ik = __shfl_sync(FULL_MASK, id, p * 8 + k);
            f[k] = ldg_feat2(f2 + (long)ik * 32 + l, polL);   // 32 lanes = full 256B row
            w[k] = ak * T;
            T *= (1.0f - ak);
        }
        float ax = 0.0f, ay = 0.0f;
        #pragma unroll
        for (int k = 0; k < K; ++k) {
            ax = fmaf(w[k], f[k].x, ax);
            ay = fmaf(w[k], f[k].y, ay);
        }
        const int col = wp * 4 + p;
        s[(2 * l)     * 33 + col] = ax;
        s[(2 * l + 1) * 33 + col] = ay;
    }
    __syncthreads();

    // ---- coalesced transposed writeout: out[b][c][h][w0..w0+31] ----
    const int b  = tileBase >> 16;        // / (H*W)
    const int hw = tileBase & 65535;
    const int h  = hw >> 8;
    const int w0 = hw & 255;              // multiple of 32
    float* obase = out + ((long)b * C) * 65536 + (long)h * 256 + w0;

    #pragma unroll
    for (int it = 0; it < 8; ++it) {
        const int c = it * 8 + wp;
        stg_stream_f(obase + (long)c * 65536 + l, s[c * 33 + l], polF);
    }
}

extern "C" void kernel_launch(void* const* d_in, const int* in_sizes, int n_in,
                              void* d_out, int out_size) {
    const float* dist = (const float*)d_in[0];
    const float* zbuf = (const float*)d_in[1];
    const int*   pidx = (const int*)d_in[2];
    const float* feat = (const float*)d_in[3];
    float* out = (float*)d_out;

    const int nPix = 8 * 256 * 256;       // 524288
    rast_blend_kernel<<<nPix / 32, 256>>>(dist, zbuf, pidx, feat, out);
}

// round 6
// speedup vs baseline: 1.3309x; 1.3309x over previous
#include <cuda_runtime.h>

#define FULL_MASK 0xFFFFFFFFu

__device__ __forceinline__ unsigned long long mk_policy_last() {
    unsigned long long pol;
    asm volatile("createpolicy.fractional.L2::evict_last.b64 %0, 1.0;" : "=l"(pol));
    return pol;
}

__device__ __forceinline__ float2 ldg_feat2(const float2* p, unsigned long long pol) {
    float2 v;
    asm volatile("ld.global.nc.L2::cache_hint.v2.f32 {%0,%1}, [%2], %3;"
                 : "=f"(v.x), "=f"(v.y) : "l"(p), "l"(pol));
    return v;
}

// Problem constants
// B=8, H=256, W=256, K=8, C=64, N=B*H*W=524288
// R_NDC = 1.5/256*2 = 3/256; R_NDC^2 = 9/65536 (exact in binary)
__global__ __launch_bounds__(256, 6) void rast_blend_kernel(
    const float* __restrict__ dist,
    const float* __restrict__ zbuf,
    const int*   __restrict__ pidx,
    const float* __restrict__ feat,
    float*       __restrict__ out)
{
    constexpr int C = 64;
    constexpr int K = 8;
    constexpr float INV_R2 = 65536.0f / 9.0f;

    __shared__ float s[C * 33];   // [channel][pixel-in-tile], pad 33 for readout

    const int tid = threadIdx.x;
    const int wp  = tid >> 5;     // warp id 0..7
    const int l   = tid & 31;     // lane

    const int tileBase = blockIdx.x * 32;     // first pixel (linear over B*H*W)
    const int warpPix  = tileBase + wp * 4;   // this warp: 4 consecutive pixels

    const unsigned long long polL = mk_policy_last();

    // ---- header: 4 pixels x K=8 = 32 contiguous entries, one coalesced load each ----
    const long hdr = (long)warpPix * K + l;
    float d  = __ldcs(dist + hdr);
    float z  = __ldcs(zbuf + hdr);
    int   id = __ldcs(pidx + hdr);

    float a = 1.0f - sqrtf(fminf(fmaxf(d * INV_R2, 0.001f), 1.0f));
    bool valid = (z >= 0.0f) && (id >= 0);
    a  = valid ? a : 0.0f;
    id = (id < 0) ? 0 : id;       // safe gather index (weight already zeroed)

    const float2* __restrict__ f2 = reinterpret_cast<const float2*>(feat);

    #pragma unroll
    for (int p = 0; p < 4; ++p) {
        // weights (warp-uniform per k); T>0 always, so w[k]==0 iff slot empty
        float w[K];
        {
            float T = 1.0f;
            #pragma unroll
            for (int k = 0; k < K; ++k) {
                float ak = __shfl_sync(FULL_MASK, a, p * 8 + k);
                w[k] = ak * T;
                T *= (1.0f - ak);
            }
        }

        float ax = 0.0f, ay = 0.0f;
        // two batches of 4 gathers: MLP=4 without flooding the L1tex queue.
        // loads predicated on warp-uniform w[k]!=0 -> empty slots (~14%) cost
        // no memory traffic but keep the code straight-line.
        #pragma unroll
        for (int half = 0; half < 2; ++half) {
            float2 f[4];
            #pragma unroll
            for (int j = 0; j < 4; ++j) {
                const int k = half * 4 + j;
                int ik = __shfl_sync(FULL_MASK, id, p * 8 + k);
                f[j] = make_float2(0.f, 0.f);
                if (w[k] != 0.0f)                       // warp-uniform predicate
                    f[j] = ldg_feat2(f2 + (long)ik * 32 + l, polL);
            }
            #pragma unroll
            for (int j = 0; j < 4; ++j) {
                const int k = half * 4 + j;
                ax = fmaf(w[k], f[j].x, ax);
                ay = fmaf(w[k], f[j].y, ay);
            }
        }

        const int col = wp * 4 + p;
        s[(2 * l)     * 33 + col] = ax;
        s[(2 * l + 1) * 33 + col] = ay;
    }
    __syncthreads();

    // ---- coalesced transposed writeout: out[b][c][h][w0..w0+31] ----
    const int b  = tileBase >> 16;        // / (H*W)
    const int hw = tileBase & 65535;
    const int h  = hw >> 8;
    const int w0 = hw & 255;              // multiple of 32
    float* obase = out + ((long)b * C) * 65536 + (long)h * 256 + w0;

    #pragma unroll
    for (int it = 0; it < 8; ++it) {
        const int c = it * 8 + wp;
        __stcs(obase + (long)c * 65536 + l, s[c * 33 + l]);
    }
}

extern "C" void kernel_launch(void* const* d_in, const int* in_sizes, int n_in,
                              void* d_out, int out_size) {
    const float* dist = (const float*)d_in[0];
    const float* zbuf = (const float*)d_in[1];
    const int*   pidx = (const int*)d_in[2];
    const float* feat = (const float*)d_in[3];
    float* out = (float*)d_out;

    const int nPix = 8 * 256 * 256;       // 524288
    rast_blend_kernel<<<nPix / 32, 256>>>(dist, zbuf, pidx, feat, out);
}